// round 9
// baseline (speedup 1.0000x reference)
#include <cuda_runtime.h>

#define NPR     16384            // values per row
#define NBINS   100
#define NROWS   4096
#define THREADS 256
#define NSUB    (THREADS / 16)   // 16 half-warp sub-histograms
#define HSTRIDE 104              // padded stride (104 % 32 == 8 -> bank shift between regions)
#define F4_PER_THREAD (NPR / (4 * THREADS))  // 16
#define BATCH   8                // float4 staged per batch (true MLP target)
#define CTAS    (152 * 4)        // persistent grid: GB300 has 152 SMs, occ-capped 4 CTA/SM

// minBlocksPerMultiprocessor=4 -> 64 regs/thread budget so the 8x float4
// staging (32 regs of data) survives ptxas instead of collapsing to
// regs=32 / MLP~3 (observed R3/R4 at default occupancy).
__global__ __launch_bounds__(THREADS, 4)
void hist_rows_kernel(const float* __restrict__ x, float* __restrict__ out)
{
    __shared__ int hist[NSUB * HSTRIDE];

    const int tid = threadIdx.x;
    // Half-warp-private histogram region
    int* h = &hist[(tid >> 4) * HSTRIDE];

    // Persistent CTAs: each handles rows bid, bid+CTAS, ... (~7 rows).
    // Kills ~6 wave transitions (~2360 cyc each) + 3488 CTA launches.
    for (int row = blockIdx.x; row < NROWS; row += CTAS) {

        #pragma unroll
        for (int i = tid; i < NSUB * HSTRIDE; i += THREADS)
            hist[i] = 0;
        __syncthreads();

        const float4* p =
            reinterpret_cast<const float4*>(x) + (size_t)row * (NPR / 4) + tid;

        #pragma unroll
        for (int outer = 0; outer < F4_PER_THREAD / BATCH; outer++) {
            // Stage BATCH loads: 8 independent LDG.128 in flight per warp
            float4 v[BATCH];
            #pragma unroll
            for (int j = 0; j < BATCH; j++)
                v[j] = __ldcs(p + (outer * BATCH + j) * THREADS);

            // Convert ALL bins first (independent F2I/IMAD chains overlap).
            // Exact ref semantics: floor(100*trunc(x)/256) == (xi*100)>>8
            // (100*xi < 2^16 exactly representable; /256 power of two).
            int b[BATCH][4];
            #pragma unroll
            for (int j = 0; j < BATCH; j++) {
                b[j][0] = ((int)v[j].x * NBINS) >> 8;
                b[j][1] = ((int)v[j].y * NBINS) >> 8;
                b[j][2] = ((int)v[j].z * NBINS) >> 8;
                b[j][3] = ((int)v[j].w * NBINS) >> 8;
            }

            // Drain into shared atomics (no-return -> REDS, no scoreboard wait)
            #pragma unroll
            for (int j = 0; j < BATCH; j++) {
                atomicAdd(&h[b[j][0]], 1);
                atomicAdd(&h[b[j][1]], 1);
                atomicAdd(&h[b[j][2]], 1);
                atomicAdd(&h[b[j][3]], 1);
            }
        }
        __syncthreads();

        // Reduce 16 sub-histograms and emit float counts
        for (int bb = tid; bb < NBINS; bb += THREADS) {
            int s = 0;
            #pragma unroll
            for (int w = 0; w < NSUB; w++)
                s += hist[w * HSTRIDE + bb];
            out[(size_t)row * NBINS + bb] = (float)s;
        }
        __syncthreads();   // protect hist from next iteration's zeroing
    }
}

extern "C" void kernel_launch(void* const* d_in, const int* in_sizes, int n_in,
                              void* d_out, int out_size)
{
    const float* x = (const float*)d_in[0];
    float* out = (float*)d_out;
    hist_rows_kernel<<<CTAS, THREADS>>>(x, out);
}

// round 10
// speedup vs baseline: 1.0092x; 1.0092x over previous
#include <cuda_runtime.h>

#define NPR     16384            // values per row
#define NBINS   100
#define THREADS 256
#define NSUB    (THREADS / 16)   // 16 half-warp sub-histograms
#define HSTRIDE 104              // padded stride (104 % 32 == 8 -> bank shift between regions)
#define F4_PER_THREAD (NPR / (4 * THREADS))  // 16
#define BATCH   4                // staged float4 per batch (fits default reg budget)
#define NBATCH  (F4_PER_THREAD / BATCH)      // 4

__global__ __launch_bounds__(THREADS)
void hist_rows_kernel(const float* __restrict__ x, float* __restrict__ out)
{
    __shared__ int hist[NSUB * HSTRIDE];

    const int tid = threadIdx.x;
    int* h = &hist[(tid >> 4) * HSTRIDE];   // half-warp-private region

    const float4* p =
        reinterpret_cast<const float4*>(x) + (size_t)blockIdx.x * (NPR / 4) + tid;

    // Prefetch batch 0 BEFORE zeroing smem: the row's first DRAM latency
    // (~600 cyc) hides under the zero-loop + barrier instead of after it.
    float4 v[BATCH];
    #pragma unroll
    for (int j = 0; j < BATCH; j++)
        v[j] = __ldcs(p + j * THREADS);

    #pragma unroll
    for (int i = tid; i < NSUB * HSTRIDE; i += THREADS)
        hist[i] = 0;
    __syncthreads();

    #pragma unroll
    for (int outer = 0; outer < NBATCH; outer++) {
        // Compute all bins of the staged batch.
        // Exact ref semantics: floor(100*trunc(x)/256) == (xi*100)>>8
        // (100*xi < 2^16 exactly representable; /256 is a power of two).
        int b[BATCH][4];
        #pragma unroll
        for (int j = 0; j < BATCH; j++) {
            b[j][0] = ((int)v[j].x * NBINS) >> 8;
            b[j][1] = ((int)v[j].y * NBINS) >> 8;
            b[j][2] = ((int)v[j].z * NBINS) >> 8;
            b[j][3] = ((int)v[j].w * NBINS) >> 8;
        }

        // Prefetch next batch before draining atomics: loads issue ahead
        // of the ~100-cyc ATOMS drain, keeping LDG pressure continuous.
        if (outer + 1 < NBATCH) {
            #pragma unroll
            for (int j = 0; j < BATCH; j++)
                v[j] = __ldcs(p + ((outer + 1) * BATCH + j) * THREADS);
        }

        // Drain into shared atomics (no-return form)
        #pragma unroll
        for (int j = 0; j < BATCH; j++) {
            atomicAdd(&h[b[j][0]], 1);
            atomicAdd(&h[b[j][1]], 1);
            atomicAdd(&h[b[j][2]], 1);
            atomicAdd(&h[b[j][3]], 1);
        }
    }
    __syncthreads();

    // Reduce 16 sub-histograms; non-temporal store (tiny output, skip L2 dwell)
    for (int bb = tid; bb < NBINS; bb += THREADS) {
        int s = 0;
        #pragma unroll
        for (int w = 0; w < NSUB; w++)
            s += hist[w * HSTRIDE + bb];
        __stwt(&out[(size_t)blockIdx.x * NBINS + bb], (float)s);
    }
}

extern "C" void kernel_launch(void* const* d_in, const int* in_sizes, int n_in,
                              void* d_out, int out_size)
{
    const float* x = (const float*)d_in[0];
    float* out = (float*)d_out;
    const int rows = out_size / NBINS;   // 4096
    hist_rows_kernel<<<rows, THREADS>>>(x, out);
}